// round 11
// baseline (speedup 1.0000x reference)
#include <cuda_runtime.h>
#include <cuda_fp16.h>
#include <cstdint>

// Inputs (metadata order):
// 0: x [N,64] f32   1: node_batch [N] int32-or-int64 (sorted)  2: global_attr [B,3] f32
// 3: Wg [3,64] f32  4: bg [64] f32  5: Wn [128,64] f32  6: bn [64] f32
// 7: Wa [64,1] f32  8: ba [1] f32
// out: w [N,1] f32   (holds score s between k_main and k_soft)

#define BMAX 8192
#define BMSK (BMAX - 1)
#define CBLK 64   // c-compute blocks

__device__ float d_c[BMAX * 64];               // c[b] = ga_b @ M + v
__device__ __align__(16) __half d_Bh[64 * 64]; // Wn[0:64] preconverted to f16
__device__ int   d_start[BMAX];                // zero BSS; empty segs -> start==end==0 skip
__device__ int   d_end[BMAX];
__device__ int   d_is64;

// ---------------- helpers ----------------

__device__ __forceinline__ uint32_t s2u(const void* p) {
    return (uint32_t)__cvta_generic_to_shared(p);
}
__device__ __forceinline__ void ldm_x4(uint32_t* r, uint32_t addr) {
    asm volatile("ldmatrix.sync.aligned.m8n8.x4.shared.b16 {%0,%1,%2,%3}, [%4];"
                 : "=r"(r[0]), "=r"(r[1]), "=r"(r[2]), "=r"(r[3]) : "r"(addr));
}
__device__ __forceinline__ void ldm_x4t(uint32_t* r, uint32_t addr) {
    asm volatile("ldmatrix.sync.aligned.m8n8.x4.trans.shared.b16 {%0,%1,%2,%3}, [%4];"
                 : "=r"(r[0]), "=r"(r[1]), "=r"(r[2]), "=r"(r[3]) : "r"(addr));
}
__device__ __forceinline__ void mma16816(float* d, const uint32_t* a, const uint32_t* b) {
    asm volatile("mma.sync.aligned.m16n8k16.row.col.f32.f16.f16.f32 "
                 "{%0,%1,%2,%3}, {%4,%5,%6,%7}, {%8,%9}, {%0,%1,%2,%3};"
                 : "+f"(d[0]), "+f"(d[1]), "+f"(d[2]), "+f"(d[3])
                 : "r"(a[0]), "r"(a[1]), "r"(a[2]), "r"(a[3]), "r"(b[0]), "r"(b[1]));
}
__device__ __forceinline__ int seg_at(const void* nbraw, int i) {
    if (d_is64) return ((int)((const long long*)nbraw)[i]) & BMSK;
    return ((const int*)nbraw)[i] & BMSK;
}
// stable softplus via EX2/LG2 (MUFU pipe, overlaps with FMA dots)
__device__ __forceinline__ float softplusf(float z) {
    float az = fabsf(z);
    float t = az * -1.4426950408889634f;
    float p, l;
    asm("ex2.approx.ftz.f32 %0, %1;" : "=f"(p) : "f"(t));
    float op = 1.0f + p;
    asm("lg2.approx.ftz.f32 %0, %1;" : "=f"(l) : "f"(op));
    return fmaxf(z, 0.0f) + 0.6931471805599453f * l;
}
__device__ __forceinline__ float exp2a(float t) {
    float e;
    asm("ex2.approx.ftz.f32 %0, %1;" : "=f"(e) : "f"(t));
    return e;
}
__device__ __forceinline__ int detect64(const int* __restrict__ p32, int n) {
    int last = n - 1;
    if (!(last & 1)) last--;
    int acc = 0;
#pragma unroll
    for (int k = 0; k < 8; k++) {
        int idx = last - 2 * k;
        if (idx >= 1) acc |= p32[idx];
    }
    return (acc == 0) ? 1 : 0;
}

// ---------------- kernel 1: prework (small) ----------------
// block 0:            dtype detect + d_Bh convert
// blocks [1, 1+CBLK): c[b] = ga_b @ M + v  (M = Wg@Wn2, v = bg@Wn2+bn)
__global__ void __launch_bounds__(256)
k_pre(const int* __restrict__ p32, int n, int B,
      const float* __restrict__ Wn, const float* __restrict__ ga,
      const float* __restrict__ Wg, const float* __restrict__ bg,
      const float* __restrict__ bn) {
    const int bid = blockIdx.x;
    const int tid = threadIdx.x;

    if (bid == 0) {
        if (tid == 0) d_is64 = detect64(p32, n);
        for (int i = tid; i < 4096; i += 256)
            d_Bh[i] = __float2half(Wn[i]);
        return;
    }

    __shared__ float sM[3][64];
    __shared__ float sv[64];
    {
        int r = tid >> 6;       // 0..3
        int j = tid & 63;
        float acc = (r == 3) ? bn[j] : 0.0f;
        const float* coef = (r == 3) ? bg : (Wg + r * 64);
#pragma unroll
        for (int i = 0; i < 64; i++)
            acc = fmaf(coef[i], Wn[(64 + i) * 64 + j], acc);
        if (r == 3) sv[j] = acc;
        else sM[r][j] = acc;
    }
    __syncthreads();
    int gpb = (B + CBLK - 1) / CBLK;
    int b0 = (bid - 1) * gpb;
    int sub = tid >> 6;
    int j = tid & 63;
    for (int it = 0; it < (gpb + 3) / 4; it++) {
        int b = b0 + it * 4 + sub;
        if (b < B && b < b0 + gpb) {
            float a0 = ga[b * 3 + 0], a1 = ga[b * 3 + 1], a2 = ga[b * 3 + 2];
            float acc = sv[j];
            acc = fmaf(a0, sM[0][j], acc);
            acc = fmaf(a1, sM[1][j], acc);
            acc = fmaf(a2, sM[2][j], acc);
            d_c[b * 64 + j] = acc;
        }
    }
}

// ---------------- kernel 2: fused GEMM + softplus + dot -> s (+ embedded boundary scan) ----------------

#define LDA 72
#define LDB 72

__global__ void __launch_bounds__(256)
k_main(const float* __restrict__ x, const void* __restrict__ nbraw,
       const float* __restrict__ Wa, const float* __restrict__ ba,
       float* __restrict__ out, int n) {
    __shared__ __align__(16) __half smA[128 * LDA];
    __shared__ __align__(16) __half smB[64 * LDB];
    __shared__ float sWa[64];
    __shared__ float sba;

    const int tid = threadIdx.x;
    const int wid = tid >> 5;
    const int lane = tid & 31;
    const int wbase = wid * 16;     // 8 warps x 16 rows
    const int r0 = blockIdx.x * 128;

    if (tid == 0) sba = ba[0];
    if (tid < 64) sWa[tid] = Wa[tid];

    // B from preconverted f16 global: 512 uint4
#pragma unroll
    for (int q = 0; q < 2; q++) {
        int j = q * 256 + tid;
        int row = j >> 3, c8 = (j & 7) * 8;
        uint4 v = reinterpret_cast<const uint4*>(d_Bh)[j];
        *reinterpret_cast<uint4*>(smB + row * LDB + c8) = v;
    }

    // A = x tile [128,64] f32 -> f16, coalesced f4 mapping (zero-pad tail rows)
#pragma unroll
    for (int it = 0; it < 8; it++) {
        int f4 = it * 256 + tid;
        int row = f4 >> 4;
        int c4 = (f4 & 15) * 4;
        int g = r0 + row;
        float4 v = make_float4(0.f, 0.f, 0.f, 0.f);
        if (g < n) v = *reinterpret_cast<const float4*>(x + (long long)g * 64 + c4);
        __half2 h0 = __floats2half2_rn(v.x, v.y);
        __half2 h1 = __floats2half2_rn(v.z, v.w);
        uint2 pv;
        pv.x = *reinterpret_cast<uint32_t*>(&h0);
        pv.y = *reinterpret_cast<uint32_t*>(&h1);
        *reinterpret_cast<uint2*>(smA + row * LDA + c4) = pv;
    }

    // ---- embedded segment-boundary scan: warp 7 scans ids [r0, r0+128) ----
    if (wid == 7) {
        int i0 = r0 + lane * 4;
        if (i0 < n) {
            if (d_is64) {
                const long long* p = (const long long*)nbraw;
                for (int i = i0; i < i0 + 4 && i < n; i++) {
                    int v = ((int)p[i]) & BMSK;
                    if (i == 0) d_start[v] = 0;
                    if (i + 1 == n) d_end[v] = n;
                    else {
                        int nx = ((int)p[i + 1]) & BMSK;
                        if (nx != v) { d_end[v] = i + 1; d_start[nx] = i + 1; }
                    }
                }
            } else {
                const int* p = (const int*)nbraw;
                int4 v4;
                if (i0 + 3 < n) v4 = *reinterpret_cast<const int4*>(p + i0);
                else {
                    v4.x = p[i0];
                    v4.y = (i0 + 1 < n) ? p[i0 + 1] : v4.x;
                    v4.z = (i0 + 2 < n) ? p[i0 + 2] : v4.y;
                    v4.w = (i0 + 3 < n) ? p[i0 + 3] : v4.z;
                }
                int a = v4.x & BMSK, b = v4.y & BMSK, c = v4.z & BMSK, d = v4.w & BMSK;
                if (i0 == 0) d_start[a] = 0;
                if (b != a && i0 + 1 < n) { d_end[a] = i0 + 1; d_start[b] = i0 + 1; }
                if (c != b && i0 + 2 < n) { d_end[b] = i0 + 2; d_start[c] = i0 + 2; }
                if (d != c && i0 + 3 < n) { d_end[c] = i0 + 3; d_start[d] = i0 + 3; }
                if (i0 + 4 >= n) d_end[(p[n - 1] & BMSK)] = n;
                else {
                    int nx = p[i0 + 4] & BMSK;
                    if (nx != d) { d_end[d] = i0 + 4; d_start[nx] = i0 + 4; }
                }
            }
        }
    }
    __syncthreads();

    const uint32_t aA = s2u(smA), aB = s2u(smB);

    // Warp computes rows [wbase, wbase+16) x cols [0,64), K=64
    float d[8][4];
#pragma unroll
    for (int nt = 0; nt < 8; nt++)
#pragma unroll
        for (int q = 0; q < 4; q++) d[nt][q] = 0.f;

#pragma unroll
    for (int kk = 0; kk < 4; kk++) {
        uint32_t a[4];
        {
            uint32_t addr = aA + ((wbase + (lane & 15)) * LDA +
                                  kk * 16 + ((lane >> 4) << 3)) * 2;
            ldm_x4(a, addr);
        }
        uint32_t b[16];
#pragma unroll
        for (int np = 0; np < 4; np++) {
            uint32_t addr = aB + ((kk * 16 + (lane & 15)) * LDB +
                                  np * 16 + ((lane >> 4) << 3)) * 2;
            ldm_x4t(b + np * 4, addr);
        }
#pragma unroll
        for (int nt = 0; nt < 8; nt++)
            mma16816(d[nt], a, b + nt * 2);
    }

    // Epilogue: thread holds rows {wbase+g8, wbase+g8+8}, cols {8nt+2l3, 8nt+2l3+1}
    const int g8 = lane >> 2;
    const int l3 = lane & 3;

    float2 wv[8];
#pragma unroll
    for (int nt = 0; nt < 8; nt++)
        wv[nt] = *reinterpret_cast<const float2*>(sWa + nt * 8 + 2 * l3);

#pragma unroll
    for (int h = 0; h < 2; h++) {
        int gr = r0 + wbase + h * 8 + g8;
        int sg = (gr < n) ? seg_at(nbraw, gr) : 0;
        const float2* cp = reinterpret_cast<const float2*>(d_c + sg * 64);
        float acc = 0.f;
#pragma unroll
        for (int nt = 0; nt < 8; nt++) {
            float2 cc = __ldg(cp + nt * 4 + l3);
            float v0 = d[nt][h * 2 + 0] + cc.x;
            float v1 = d[nt][h * 2 + 1] + cc.y;
            acc = fmaf(wv[nt].x, softplusf(v0), acc);
            acc = fmaf(wv[nt].y, softplusf(v1), acc);
        }
        acc += __shfl_xor_sync(0xFFFFFFFFu, acc, 1);
        acc += __shfl_xor_sync(0xFFFFFFFFu, acc, 2);
        if (l3 == 0 && gr < n) out[gr] = acc + sba;
    }
}

// ---------------- kernel 3: warp-per-graph softmax (precomputed bounds) ----------------

#define CH 8   // register-cached elements per lane (covers count <= 256)

__global__ void __launch_bounds__(256)
k_soft(float* __restrict__ out, int n, int B) {
    const int b = blockIdx.x * 8 + (threadIdx.x >> 5);
    if (b >= B) return;
    const int lane = threadIdx.x & 31;
    int start = d_start[b];
    int end = d_end[b];
    if (end > n) end = n;
    if (start >= end) return;

    float vals[CH];
    float lm = __int_as_float(0xFF800000);
#pragma unroll
    for (int c = 0; c < CH; c++) {
        int i = start + lane + c * 32;
        if (i < end) { vals[c] = out[i]; lm = fmaxf(lm, vals[c]); }
    }
    for (int i = start + lane + CH * 32; i < end; i += 32)
        lm = fmaxf(lm, out[i]);

#pragma unroll
    for (int off = 16; off; off >>= 1)
        lm = fmaxf(lm, __shfl_xor_sync(0xFFFFFFFFu, lm, off));
    const float m = lm;

    float ls = 0.f;
#pragma unroll
    for (int c = 0; c < CH; c++) {
        int i = start + lane + c * 32;
        if (i < end) {
            float e = exp2a((vals[c] - m) * 1.4426950408889634f);
            vals[c] = e;
            ls += e;
        }
    }
    for (int i = start + lane + CH * 32; i < end; i += 32)
        ls += exp2a((out[i] - m) * 1.4426950408889634f);

#pragma unroll
    for (int off = 16; off; off >>= 1)
        ls += __shfl_xor_sync(0xFFFFFFFFu, ls, off);
    const float inv = 1.0f / (ls + 1e-16f);

#pragma unroll
    for (int c = 0; c < CH; c++) {
        int i = start + lane + c * 32;
        if (i < end) out[i] = vals[c] * inv;
    }
    for (int i = start + lane + CH * 32; i < end; i += 32)
        out[i] = exp2a((out[i] - m) * 1.4426950408889634f) * inv;
}

// ---------------- launch ----------------

extern "C" void kernel_launch(void* const* d_in, const int* in_sizes, int n_in,
                              void* d_out, int out_size) {
    const float* x = (const float*)d_in[0];
    const void* nb = d_in[1];
    const float* ga = (const float*)d_in[2];
    const float* Wg = (const float*)d_in[3];
    const float* bg = (const float*)d_in[4];
    const float* Wn = (const float*)d_in[5];
    const float* bn = (const float*)d_in[6];
    const float* Wa = (const float*)d_in[7];
    const float* ba = (const float*)d_in[8];
    float* out = (float*)d_out;

    int n = in_sizes[0] / 64;
    if (n > out_size) n = out_size;
    int B = in_sizes[2] / 3;
    if (B > BMAX) B = BMAX;

    k_pre<<<1 + CBLK, 256>>>((const int*)nb, n, B, Wn, ga, Wg, bg, bn);

    int tiles = (n + 127) / 128;
    k_main<<<tiles, 256>>>(x, nb, Wa, ba, out, n);

    k_soft<<<(B + 7) / 8, 256>>>(out, n, B);
}

// round 12
// speedup vs baseline: 1.0781x; 1.0781x over previous
#include <cuda_runtime.h>
#include <cuda_fp16.h>
#include <cstdint>

// Inputs (metadata order):
// 0: x [N,64] f32   1: node_batch [N] int32-or-int64 (sorted)  2: global_attr [B,3] f32
// 3: Wg [3,64] f32  4: bg [64] f32  5: Wn [128,64] f32  6: bn [64] f32
// 7: Wa [64,1] f32  8: ba [1] f32
// out: w [N,1] f32   (holds score s between k_main and k_soft)

#define BMAX 8192
#define BMSK (BMAX - 1)

__device__ float d_c[BMAX * 64];               // c[b] = (ga_b@Wg+bg) @ Wn[64:] + bn
__device__ __align__(16) __half d_Bh[64 * 64]; // Wn[0:64] preconverted to f16
__device__ int   d_start[BMAX];                // zero BSS; empty segs -> start==end==0 skip
__device__ int   d_end[BMAX];
__device__ int   d_is64;

// ---------------- helpers ----------------

__device__ __forceinline__ uint32_t s2u(const void* p) {
    return (uint32_t)__cvta_generic_to_shared(p);
}
__device__ __forceinline__ void ldm_x4(uint32_t* r, uint32_t addr) {
    asm volatile("ldmatrix.sync.aligned.m8n8.x4.shared.b16 {%0,%1,%2,%3}, [%4];"
                 : "=r"(r[0]), "=r"(r[1]), "=r"(r[2]), "=r"(r[3]) : "r"(addr));
}
__device__ __forceinline__ void ldm_x4t(uint32_t* r, uint32_t addr) {
    asm volatile("ldmatrix.sync.aligned.m8n8.x4.trans.shared.b16 {%0,%1,%2,%3}, [%4];"
                 : "=r"(r[0]), "=r"(r[1]), "=r"(r[2]), "=r"(r[3]) : "r"(addr));
}
__device__ __forceinline__ void mma16816(float* d, const uint32_t* a, const uint32_t* b) {
    asm volatile("mma.sync.aligned.m16n8k16.row.col.f32.f16.f16.f32 "
                 "{%0,%1,%2,%3}, {%4,%5,%6,%7}, {%8,%9}, {%0,%1,%2,%3};"
                 : "+f"(d[0]), "+f"(d[1]), "+f"(d[2]), "+f"(d[3])
                 : "r"(a[0]), "r"(a[1]), "r"(a[2]), "r"(a[3]), "r"(b[0]), "r"(b[1]));
}
__device__ __forceinline__ int seg_at(const void* nbraw, int i) {
    if (d_is64) return ((int)((const long long*)nbraw)[i]) & BMSK;
    return ((const int*)nbraw)[i] & BMSK;
}
// stable softplus via EX2/LG2 (MUFU pipe, overlaps with FMA dots)
__device__ __forceinline__ float softplusf(float z) {
    float az = fabsf(z);
    float t = az * -1.4426950408889634f;
    float p, l;
    asm("ex2.approx.ftz.f32 %0, %1;" : "=f"(p) : "f"(t));
    float op = 1.0f + p;
    asm("lg2.approx.ftz.f32 %0, %1;" : "=f"(l) : "f"(op));
    return fmaxf(z, 0.0f) + 0.6931471805599453f * l;
}
__device__ __forceinline__ float exp2a(float t) {
    float e;
    asm("ex2.approx.ftz.f32 %0, %1;" : "=f"(e) : "f"(t));
    return e;
}
__device__ __forceinline__ int detect64(const int* __restrict__ p32, int n) {
    int last = n - 1;
    if (!(last & 1)) last--;
    int acc = 0;
#pragma unroll
    for (int k = 0; k < 8; k++) {
        int idx = last - 2 * k;
        if (idx >= 1) acc |= p32[idx];
    }
    return (acc == 0) ? 1 : 0;
}

// ---------------- kernel 1: merged prework (R9 structure: all blocks parallel) ----------------
// block 0:            dtype detect + d_Bh convert
// blocks [1, 1+GB):   per-graph c[b], 4 graphs per block (direct 64-deep, no serial loop)
// blocks [1+GB, ...): segment boundary scan (vectorized, no atomics)
__global__ void __launch_bounds__(256)
k_pre(const int* __restrict__ p32, int n, int B, int GB,
      const float* __restrict__ Wn, const float* __restrict__ ga,
      const float* __restrict__ Wg, const float* __restrict__ bg,
      const float* __restrict__ bn) {
    const int bid = blockIdx.x;
    const int tid = threadIdx.x;

    if (bid == 0) {
        if (tid == 0) d_is64 = detect64(p32, n);
        for (int i = tid; i < 4096; i += 256)
            d_Bh[i] = __float2half(Wn[i]);
        return;
    }

    if (bid <= GB) {
        __shared__ float g[4][65];
        int sub = tid >> 6;
        int j = tid & 63;
        int b = (bid - 1) * 4 + sub;
        if (b < B) {
            float a0 = ga[b * 3 + 0], a1 = ga[b * 3 + 1], a2 = ga[b * 3 + 2];
            g[sub][j] = bg[j] + a0 * Wg[j] + a1 * Wg[64 + j] + a2 * Wg[128 + j];
        }
        __syncthreads();
        if (b < B) {
            float acc = bn[j];
#pragma unroll
            for (int i = 0; i < 64; i++)
                acc = fmaf(g[sub][i], Wn[(64 + i) * 64 + j], acc);
            d_c[b * 64 + j] = acc;
        }
        return;
    }

    // boundary scan; local dtype detect (tail words are cache-hot)
    __shared__ int sIs64;
    if (tid == 0) sIs64 = detect64(p32, n);
    __syncthreads();
    const int is64 = sIs64;

    int i0 = ((bid - 1 - GB) * 256 + tid) * 4;
    if (i0 >= n) return;

    if (is64) {
        const long long* p = (const long long*)p32;
        for (int i = i0; i < i0 + 4 && i < n; i++) {
            int v = ((int)p[i]) & BMSK;
            if (i == 0) d_start[v] = 0;
            if (i + 1 == n) d_end[v] = n;
            else {
                int nx = ((int)p[i + 1]) & BMSK;
                if (nx != v) { d_end[v] = i + 1; d_start[nx] = i + 1; }
            }
        }
        return;
    }
    const int* p = p32;
    int4 v4;
    if (i0 + 3 < n) v4 = *reinterpret_cast<const int4*>(p + i0);
    else {
        v4.x = p[i0];
        v4.y = (i0 + 1 < n) ? p[i0 + 1] : v4.x;
        v4.z = (i0 + 2 < n) ? p[i0 + 2] : v4.y;
        v4.w = (i0 + 3 < n) ? p[i0 + 3] : v4.z;
    }
    int a = v4.x & BMSK, b = v4.y & BMSK, c = v4.z & BMSK, d = v4.w & BMSK;
    if (i0 == 0) d_start[a] = 0;
    if (b != a && i0 + 1 < n) { d_end[a] = i0 + 1; d_start[b] = i0 + 1; }
    if (c != b && i0 + 2 < n) { d_end[b] = i0 + 2; d_start[c] = i0 + 2; }
    if (d != c && i0 + 3 < n) { d_end[c] = i0 + 3; d_start[d] = i0 + 3; }
    if (i0 + 4 >= n) d_end[(p[n - 1] & BMSK)] = n;
    else {
        int nx = p[i0 + 4] & BMSK;
        if (nx != d) { d_end[d] = i0 + 4; d_start[nx] = i0 + 4; }
    }
}

// ---------------- kernel 2: fused GEMM + softplus + dot -> s (reg diet, 5 CTAs/SM) ----------------

#define LDA 72
#define LDB 72

__global__ void __launch_bounds__(256, 5)
k_main(const float* __restrict__ x, const void* __restrict__ nbraw,
       const float* __restrict__ Wa, const float* __restrict__ ba,
       float* __restrict__ out, int n) {
    __shared__ __align__(16) __half smA[128 * LDA];
    __shared__ __align__(16) __half smB[64 * LDB];
    __shared__ float sWa[64];
    __shared__ float sba;

    const int tid = threadIdx.x;
    const int wid = tid >> 5;
    const int lane = tid & 31;
    const int wbase = wid * 16;     // 8 warps x 16 rows
    const int r0 = blockIdx.x * 128;

    if (tid == 0) sba = ba[0];
    if (tid < 64) sWa[tid] = Wa[tid];

    // B from preconverted f16 global: 512 uint4
#pragma unroll
    for (int q = 0; q < 2; q++) {
        int j = q * 256 + tid;
        int row = j >> 3, c8 = (j & 7) * 8;
        uint4 v = reinterpret_cast<const uint4*>(d_Bh)[j];
        *reinterpret_cast<uint4*>(smB + row * LDB + c8) = v;
    }

    // A = x tile [128,64] f32 -> f16, coalesced f4 mapping (zero-pad tail rows)
#pragma unroll
    for (int it = 0; it < 8; it++) {
        int f4 = it * 256 + tid;
        int row = f4 >> 4;
        int c4 = (f4 & 15) * 4;
        int g = r0 + row;
        float4 v = make_float4(0.f, 0.f, 0.f, 0.f);
        if (g < n) v = *reinterpret_cast<const float4*>(x + (long long)g * 64 + c4);
        __half2 h0 = __floats2half2_rn(v.x, v.y);
        __half2 h1 = __floats2half2_rn(v.z, v.w);
        uint2 pv;
        pv.x = *reinterpret_cast<uint32_t*>(&h0);
        pv.y = *reinterpret_cast<uint32_t*>(&h1);
        *reinterpret_cast<uint2*>(smA + row * LDA + c4) = pv;
    }
    __syncthreads();

    const uint32_t aA = s2u(smA), aB = s2u(smB);

    // Warp computes rows [wbase, wbase+16) x cols [0,64), K=64
    float d[8][4];
#pragma unroll
    for (int nt = 0; nt < 8; nt++)
#pragma unroll
        for (int q = 0; q < 4; q++) d[nt][q] = 0.f;

#pragma unroll
    for (int kk = 0; kk < 4; kk++) {
        uint32_t a[4];
        {
            uint32_t addr = aA + ((wbase + (lane & 15)) * LDA +
                                  kk * 16 + ((lane >> 4) << 3)) * 2;
            ldm_x4(a, addr);
        }
        // B fragments loaded per-np and consumed immediately (live b = 4 regs)
#pragma unroll
        for (int np = 0; np < 4; np++) {
            uint32_t b4[4];
            uint32_t addr = aB + ((kk * 16 + (lane & 15)) * LDB +
                                  np * 16 + ((lane >> 4) << 3)) * 2;
            ldm_x4t(b4, addr);
            mma16816(d[np * 2 + 0], a, b4 + 0);
            mma16816(d[np * 2 + 1], a, b4 + 2);
        }
    }

    // Epilogue: thread holds rows {wbase+g8, wbase+g8+8}, cols {8nt+2l3, 8nt+2l3+1}
    const int g8 = lane >> 2;
    const int l3 = lane & 3;

#pragma unroll
    for (int h = 0; h < 2; h++) {
        int gr = r0 + wbase + h * 8 + g8;
        int sg = (gr < n) ? seg_at(nbraw, gr) : 0;
        const float2* cp = reinterpret_cast<const float2*>(d_c + sg * 64);
        float acc = 0.f;
#pragma unroll
        for (int nt = 0; nt < 8; nt++) {
            float2 cc = __ldg(cp + nt * 4 + l3);
            float2 wvv = *reinterpret_cast<const float2*>(sWa + nt * 8 + 2 * l3);
            float v0 = d[nt][h * 2 + 0] + cc.x;
            float v1 = d[nt][h * 2 + 1] + cc.y;
            acc = fmaf(wvv.x, softplusf(v0), acc);
            acc = fmaf(wvv.y, softplusf(v1), acc);
        }
        acc += __shfl_xor_sync(0xFFFFFFFFu, acc, 1);
        acc += __shfl_xor_sync(0xFFFFFFFFu, acc, 2);
        if (l3 == 0 && gr < n) out[gr] = acc + sba;
    }
}

// ---------------- kernel 3: warp-per-graph softmax (precomputed bounds) ----------------

#define CH 8   // register-cached elements per lane (covers count <= 256)

__global__ void __launch_bounds__(256)
k_soft(float* __restrict__ out, int n, int B) {
    const int b = blockIdx.x * 8 + (threadIdx.x >> 5);
    if (b >= B) return;
    const int lane = threadIdx.x & 31;
    int start = d_start[b];
    int end = d_end[b];
    if (end > n) end = n;
    if (start >= end) return;

    float vals[CH];
    float lm = __int_as_float(0xFF800000);
#pragma unroll
    for (int c = 0; c < CH; c++) {
        int i = start + lane + c * 32;
        if (i < end) { vals[c] = out[i]; lm = fmaxf(lm, vals[c]); }
    }
    for (int i = start + lane + CH * 32; i < end; i += 32)
        lm = fmaxf(lm, out[i]);

#pragma unroll
    for (int off = 16; off; off >>= 1)
        lm = fmaxf(lm, __shfl_xor_sync(0xFFFFFFFFu, lm, off));
    const float m = lm;

    float ls = 0.f;
#pragma unroll
    for (int c = 0; c < CH; c++) {
        int i = start + lane + c * 32;
        if (i < end) {
            float e = exp2a((vals[c] - m) * 1.4426950408889634f);
            vals[c] = e;
            ls += e;
        }
    }
    for (int i = start + lane + CH * 32; i < end; i += 32)
        ls += exp2a((out[i] - m) * 1.4426950408889634f);

#pragma unroll
    for (int off = 16; off; off >>= 1)
        ls += __shfl_xor_sync(0xFFFFFFFFu, ls, off);
    const float inv = 1.0f / (ls + 1e-16f);

#pragma unroll
    for (int c = 0; c < CH; c++) {
        int i = start + lane + c * 32;
        if (i < end) out[i] = vals[c] * inv;
    }
    for (int i = start + lane + CH * 32; i < end; i += 32)
        out[i] = exp2a((out[i] - m) * 1.4426950408889634f) * inv;
}

// ---------------- launch ----------------

extern "C" void kernel_launch(void* const* d_in, const int* in_sizes, int n_in,
                              void* d_out, int out_size) {
    const float* x = (const float*)d_in[0];
    const void* nb = d_in[1];
    const float* ga = (const float*)d_in[2];
    const float* Wg = (const float*)d_in[3];
    const float* bg = (const float*)d_in[4];
    const float* Wn = (const float*)d_in[5];
    const float* bn = (const float*)d_in[6];
    const float* Wa = (const float*)d_in[7];
    const float* ba = (const float*)d_in[8];
    float* out = (float*)d_out;

    int n = in_sizes[0] / 64;
    if (n > out_size) n = out_size;
    int B = in_sizes[2] / 3;
    if (B > BMAX) B = BMAX;

    int GB = (B + 3) / 4;
    int KB = (n + 1023) / 1024;
    k_pre<<<1 + GB + KB, 256>>>((const int*)nb, n, B, GB, Wn, ga, Wg, bg, bn);

    int tiles = (n + 127) / 128;
    k_main<<<tiles, 256>>>(x, nb, Wa, ba, out, n);

    k_soft<<<(B + 7) / 8, 256>>>(out, n, B);
}